// round 5
// baseline (speedup 1.0000x reference)
#include <cuda_runtime.h>
#include <stdint.h>

#define N_NODES_MAX 100000
#define E_MAX       1600000
#define CH          128
#define SCAN_BLK    512
#define SCAN_NB     ((N_NODES_MAX + SCAN_BLK - 1) / SCAN_BLK)   // 196

// ---------------- scratch (small static device globals; ~7 MB total) ---------
__device__ __align__(16) int   g_cnt[N_NODES_MAX];       // in-degree (w/o self loop)
__device__ __align__(16) int   g_rowstart[N_NODES_MAX];  // CSR row offsets
__device__ __align__(16) int   g_cursor[N_NODES_MAX];    // fill cursors
__device__ __align__(16) int   g_csr_src[E_MAX];         // src node per CSR slot
__device__ __align__(16) float g_dinv[N_NODES_MAX];
__device__ __align__(16) int   g_bsum[SCAN_NB];
__device__ __align__(16) int   g_bpre[SCAN_NB];

// ---------------- kernel 1: zero counts --------------------------------------
__global__ void k_zero(int n) {
    int i = blockIdx.x * blockDim.x + threadIdx.x;
    if (i < n) g_cnt[i] = 0;
}

// ---------------- kernel 2: count in-degree per dst ---------------------------
// edge_index is int32 [2, E]: src = ei[e], dst = ei[E + e]
__global__ void k_count(const int* __restrict__ ei, int E, int n) {
    int e = blockIdx.x * blockDim.x + threadIdx.x;
    if (e < E) {
        unsigned dst = (unsigned)ei[E + e];
        if (dst < (unsigned)n)                 // guard: never trap on bad dtype
            atomicAdd(&g_cnt[dst], 1);
    }
}

// ---------------- kernel 3a: per-block exclusive scan -------------------------
__global__ void k_scan_block(int n) {
    __shared__ int sh[SCAN_BLK];
    int tid = threadIdx.x;
    int gid = blockIdx.x * SCAN_BLK + tid;
    int v = (gid < n) ? g_cnt[gid] : 0;
    sh[tid] = v;
    __syncthreads();
    for (int off = 1; off < SCAN_BLK; off <<= 1) {
        int t = (tid >= off) ? sh[tid - off] : 0;
        __syncthreads();
        sh[tid] += t;
        __syncthreads();
    }
    if (gid < n) g_rowstart[gid] = sh[tid] - v;   // exclusive
    if (tid == SCAN_BLK - 1) g_bsum[blockIdx.x] = sh[tid];
}

// ---------------- kernel 3b: scan block sums (single block) -------------------
__global__ void k_scan_bsums(int nb) {
    __shared__ int sh[256];
    int tid = threadIdx.x;
    int v = (tid < nb) ? g_bsum[tid] : 0;
    sh[tid] = v;
    __syncthreads();
    for (int off = 1; off < 256; off <<= 1) {
        int t = (tid >= off) ? sh[tid - off] : 0;
        __syncthreads();
        sh[tid] += t;
        __syncthreads();
    }
    if (tid < nb) g_bpre[tid] = sh[tid] - v;      // exclusive
}

// ---------------- kernel 3c: add block prefix; init cursor + dinv -------------
__global__ void k_scan_add(int n) {
    int i = blockIdx.x * blockDim.x + threadIdx.x;
    if (i < n) {
        int rs = g_rowstart[i] + g_bpre[i / SCAN_BLK];
        g_rowstart[i] = rs;
        g_cursor[i]   = rs;
        g_dinv[i]     = rsqrtf(1.0f + (float)g_cnt[i]);  // +1 self loop
    }
}

// ---------------- kernel 4: CSR fill ------------------------------------------
__global__ void k_fill(const int* __restrict__ ei, int E, int n) {
    int e = blockIdx.x * blockDim.x + threadIdx.x;
    if (e < E) {
        unsigned src = (unsigned)ei[e];
        unsigned dst = (unsigned)ei[E + e];
        if (src < (unsigned)n && dst < (unsigned)n) {
            int pos = atomicAdd(&g_cursor[dst], 1);
            if ((unsigned)pos < (unsigned)E_MAX)
                g_csr_src[pos] = (int)src;
        }
    }
}

// ---------------- kernel 5: gather-aggregate (warp per node) -------------------
// agg[d] = dinv[d]^2 * x[d] + sum_{s in N(d)} dinv[s]*dinv[d] * x[s]
// Result written directly into d_out (later transformed in place by the GEMM).
__global__ void __launch_bounds__(256)
k_aggregate(const float* __restrict__ x, float* __restrict__ agg, int n) {
    int node = (blockIdx.x * blockDim.x + threadIdx.x) >> 5;
    int lane = threadIdx.x & 31;
    if (node >= n) return;

    float di = g_dinv[node];
    float4 acc = ((const float4*)(x + (size_t)node * CH))[lane];
    float ws = di * di;
    acc.x *= ws; acc.y *= ws; acc.z *= ws; acc.w *= ws;

    int start = g_rowstart[node];
    int end   = start + g_cnt[node];

    for (int p0 = start; p0 < end; p0 += 32) {
        int myp = p0 + lane;
        int s = 0; float w = 0.0f;
        if (myp < end) {
            s = g_csr_src[myp];          // coalesced within warp
            w = di * g_dinv[s];
        }
        int cnt = min(32, end - p0);
        for (int j = 0; j < cnt; j++) {
            int   sj = __shfl_sync(0xffffffffu, s, j);
            float wj = __shfl_sync(0xffffffffu, w, j);
            float4 v = ((const float4*)(x + (size_t)sj * CH))[lane];
            acc.x += wj * v.x; acc.y += wj * v.y;
            acc.z += wj * v.z; acc.w += wj * v.w;
        }
    }
    ((float4*)(agg + (size_t)node * CH))[lane] = acc;
}

// ---------------- kernel 6: in-place SGEMM  out = out @ W + bias ---------------
// Safe in place: each block reads only rows [row0,row0+128) and writes the same
// rows strictly after all of its reads; no other block touches those rows.
__global__ void __launch_bounds__(256)
k_gemm(const float* __restrict__ B,     // W [128,128]
       const float* __restrict__ bias,  // [128]
       float* C, int M) {               // C doubles as A (no restrict)
    __shared__ float As[16][128];   // [k][m]
    __shared__ float Bs[16][128];   // [k][n]

    const int tid  = threadIdx.x;
    const int row0 = blockIdx.x * 128;
    const int tr   = (tid / 16) * 8;
    const int tc   = (tid % 16) * 8;

    float acc[8][8];
#pragma unroll
    for (int i = 0; i < 8; i++)
#pragma unroll
        for (int j = 0; j < 8; j++) acc[i][j] = 0.0f;

    for (int k0 = 0; k0 < 128; k0 += 16) {
#pragma unroll
        for (int i = 0; i < 2; i++) {
            int idx = tid * 2 + i;            // 0..511
            int r   = idx >> 2;               // 0..127
            int c   = (idx & 3) * 4;          // 0,4,8,12
            float4 v = make_float4(0.f, 0.f, 0.f, 0.f);
            if (row0 + r < M)
                v = *(const float4*)(C + (size_t)(row0 + r) * CH + k0 + c);
            As[c + 0][r] = v.x; As[c + 1][r] = v.y;
            As[c + 2][r] = v.z; As[c + 3][r] = v.w;
        }
#pragma unroll
        for (int i = 0; i < 2; i++) {
            int idx = tid * 2 + i;
            int r   = idx >> 5;               // 0..15
            int c   = (idx & 31) * 4;
            *(float4*)&Bs[r][c] = *(const float4*)(B + (size_t)(k0 + r) * CH + c);
        }
        __syncthreads();

#pragma unroll
        for (int k = 0; k < 16; k++) {
            float a[8], b[8];
            *(float4*)&a[0] = *(float4*)&As[k][tr];
            *(float4*)&a[4] = *(float4*)&As[k][tr + 4];
            *(float4*)&b[0] = *(float4*)&Bs[k][tc];
            *(float4*)&b[4] = *(float4*)&Bs[k][tc + 4];
#pragma unroll
            for (int i = 0; i < 8; i++)
#pragma unroll
                for (int j = 0; j < 8; j++)
                    acc[i][j] += a[i] * b[j];
        }
        __syncthreads();
    }

    float bv[8];
    *(float4*)&bv[0] = *(const float4*)(bias + tc);
    *(float4*)&bv[4] = *(const float4*)(bias + tc + 4);

#pragma unroll
    for (int i = 0; i < 8; i++) {
        int r = row0 + tr + i;
        if (r < M) {
            float4 o0 = make_float4(acc[i][0] + bv[0], acc[i][1] + bv[1],
                                    acc[i][2] + bv[2], acc[i][3] + bv[3]);
            float4 o1 = make_float4(acc[i][4] + bv[4], acc[i][5] + bv[5],
                                    acc[i][6] + bv[6], acc[i][7] + bv[7]);
            *(float4*)(C + (size_t)r * CH + tc)     = o0;
            *(float4*)(C + (size_t)r * CH + tc + 4) = o1;
        }
    }
}

// ---------------- launch --------------------------------------------------------
extern "C" void kernel_launch(void* const* d_in, const int* in_sizes, int n_in,
                              void* d_out, int out_size) {
    const float* x    = (const float*)d_in[0];
    const int*   ei   = (const int*)d_in[1];     // int32 [2, E] (harness converts int64)
    const float* W    = (const float*)d_in[2];
    const float* bias = (const float*)d_in[3];
    float*       out  = (float*)d_out;

    int N = in_sizes[0] / CH;   // 100000
    int E = in_sizes[1] / 2;    // 1600000
    int nb = (N + SCAN_BLK - 1) / SCAN_BLK;

    k_zero      <<<(N + 255) / 256, 256>>>(N);
    k_count     <<<(E + 255) / 256, 256>>>(ei, E, N);
    k_scan_block<<<nb, SCAN_BLK>>>(N);
    k_scan_bsums<<<1, 256>>>(nb);
    k_scan_add  <<<(N + 255) / 256, 256>>>(N);
    k_fill      <<<(E + 255) / 256, 256>>>(ei, E, N);
    k_aggregate <<<(N * 32 + 255) / 256, 256>>>(x, out, N);
    k_gemm      <<<(N + 127) / 128, 256>>>(W, bias, out, N);
}

// round 6
// speedup vs baseline: 1.4273x; 1.4273x over previous
#include <cuda_runtime.h>
#include <cuda_fp16.h>
#include <mma.h>
#include <stdint.h>

using namespace nvcuda;

#define N_NODES_MAX 100000
#define N_PAD       100096            // multiple of 128 (= 782 * 128)
#define E_MAX       1600000
#define CH          128
#define SCAN_BLK    512
#define SCAN_NB     ((N_NODES_MAX + SCAN_BLK - 1) / SCAN_BLK)   // 196

// ---------------- scratch (static device globals; zero-initialized) ----------
__device__ __align__(16) int     g_cnt[N_NODES_MAX];
__device__ __align__(16) int     g_rowstart[N_NODES_MAX];
__device__ __align__(16) int     g_cursor[N_NODES_MAX];
__device__ __align__(16) int     g_csr_src[E_MAX];
__device__ __align__(16) float   g_dinv[N_NODES_MAX];
__device__ __align__(16) int     g_bsum[SCAN_NB];
__device__ __align__(16) int     g_bpre[SCAN_NB];
__device__ __align__(16) __half2 g_xh[(size_t)N_NODES_MAX * 64];   // x in fp16
__device__ __align__(16) __half2 g_aggh[(size_t)N_PAD * 64];       // agg in fp16
__device__ __align__(16) __half2 g_Wh[CH * CH / 2];                // W in fp16

// ---------------- kernel 1: zero counts + convert x,W to fp16 -----------------
__global__ void k_prep(const float2* __restrict__ x2,
                       const float2* __restrict__ W2, int n) {
    int i = blockIdx.x * blockDim.x + threadIdx.x;
    int conv = n * 64;                        // half2 elements of x
    if (i < conv) g_xh[i] = __float22half2_rn(x2[i]);
    if (i < CH * CH / 2) g_Wh[i] = __float22half2_rn(W2[i]);
    if (i < n) g_cnt[i] = 0;
}

// ---------------- kernel 2: count in-degree per dst ---------------------------
__global__ void k_count(const int* __restrict__ ei, int E, int n) {
    int e = blockIdx.x * blockDim.x + threadIdx.x;
    if (e < E) {
        unsigned dst = (unsigned)ei[E + e];
        if (dst < (unsigned)n)
            atomicAdd(&g_cnt[dst], 1);
    }
}

// ---------------- kernel 3a: per-block exclusive scan -------------------------
__global__ void k_scan_block(int n) {
    __shared__ int sh[SCAN_BLK];
    int tid = threadIdx.x;
    int gid = blockIdx.x * SCAN_BLK + tid;
    int v = (gid < n) ? g_cnt[gid] : 0;
    sh[tid] = v;
    __syncthreads();
    for (int off = 1; off < SCAN_BLK; off <<= 1) {
        int t = (tid >= off) ? sh[tid - off] : 0;
        __syncthreads();
        sh[tid] += t;
        __syncthreads();
    }
    if (gid < n) g_rowstart[gid] = sh[tid] - v;   // exclusive
    if (tid == SCAN_BLK - 1) g_bsum[blockIdx.x] = sh[tid];
}

// ---------------- kernel 3b: scan block sums (single block) -------------------
__global__ void k_scan_bsums(int nb) {
    __shared__ int sh[256];
    int tid = threadIdx.x;
    int v = (tid < nb) ? g_bsum[tid] : 0;
    sh[tid] = v;
    __syncthreads();
    for (int off = 1; off < 256; off <<= 1) {
        int t = (tid >= off) ? sh[tid - off] : 0;
        __syncthreads();
        sh[tid] += t;
        __syncthreads();
    }
    if (tid < nb) g_bpre[tid] = sh[tid] - v;      // exclusive
}

// ---------------- kernel 3c: add block prefix; init cursor + dinv -------------
__global__ void k_scan_add(int n) {
    int i = blockIdx.x * blockDim.x + threadIdx.x;
    if (i < n) {
        int rs = g_rowstart[i] + g_bpre[i / SCAN_BLK];
        g_rowstart[i] = rs;
        g_cursor[i]   = rs;
        g_dinv[i]     = rsqrtf(1.0f + (float)g_cnt[i]);  // +1 self loop
    }
}

// ---------------- kernel 4: CSR fill ------------------------------------------
__global__ void k_fill(const int* __restrict__ ei, int E, int n) {
    int e = blockIdx.x * blockDim.x + threadIdx.x;
    if (e < E) {
        unsigned src = (unsigned)ei[e];
        unsigned dst = (unsigned)ei[E + e];
        if (src < (unsigned)n && dst < (unsigned)n) {
            int pos = atomicAdd(&g_cursor[dst], 1);
            if ((unsigned)pos < (unsigned)E_MAX)
                g_csr_src[pos] = (int)src;
        }
    }
}

// ---------------- kernel 5: gather-aggregate (warp per node, fp16 gather) -----
// agg[d] = dinv[d]^2 * x[d] + sum_{s in N(d)} dinv[s]*dinv[d] * x[s]
__global__ void __launch_bounds__(256)
k_aggregate(int n) {
    int node = (blockIdx.x * blockDim.x + threadIdx.x) >> 5;
    int lane = threadIdx.x & 31;
    if (node >= n) return;

    float di = g_dinv[node];
    uint2 sv = ((const uint2*)(g_xh + (size_t)node * 64))[lane];
    float2 f0 = __half22float2(*(__half2*)&sv.x);
    float2 f1 = __half22float2(*(__half2*)&sv.y);
    float ws = di * di;
    float4 acc = make_float4(f0.x * ws, f0.y * ws, f1.x * ws, f1.y * ws);

    int start = g_rowstart[node];
    int end   = start + g_cnt[node];

    for (int p0 = start; p0 < end; p0 += 32) {
        int myp = p0 + lane;
        int s = 0; float w = 0.0f;
        if (myp < end) {
            s = g_csr_src[myp];                 // coalesced
            w = di * g_dinv[s];
        }
        int cnt = min(32, end - p0);
        for (int j = 0; j < cnt; j++) {
            int   sj = __shfl_sync(0xffffffffu, s, j);
            float wj = __shfl_sync(0xffffffffu, w, j);
            uint2 v  = ((const uint2*)(g_xh + (size_t)sj * 64))[lane];
            float2 a = __half22float2(*(__half2*)&v.x);
            float2 b = __half22float2(*(__half2*)&v.y);
            acc.x += wj * a.x; acc.y += wj * a.y;
            acc.z += wj * b.x; acc.w += wj * b.y;
        }
    }
    __half2 o0 = __floats2half2_rn(acc.x, acc.y);
    __half2 o1 = __floats2half2_rn(acc.z, acc.w);
    uint2 ov = make_uint2(*(unsigned*)&o0, *(unsigned*)&o1);
    ((uint2*)(g_aggh + (size_t)node * 64))[lane] = ov;
}

// ---------------- kernel 6: HMMA GEMM  out = agg_h @ W_h + bias ---------------
// block = 128 rows x 128 cols, 8 warps in 2(m) x 4(n); warp tile 64x32.
__global__ void __launch_bounds__(256)
k_gemm(const float* __restrict__ bias, float* __restrict__ C, int M) {
    __shared__ __align__(16) __half As[128 * 136];   // padded ld = 136
    __shared__ float Es[8 * 256];                    // per-warp 16x16 bounce

    const int tid  = threadIdx.x;
    const int wid  = tid >> 5;
    const int lane = tid & 31;
    const int row0 = blockIdx.x * 128;
    const int warp_m = wid & 1;        // 0..1  (64 rows each)
    const int warp_n = wid >> 1;       // 0..3  (32 cols each)

    // cooperative load of A tile (g_aggh is padded to N_PAD rows; always in range)
    {
        const uint4* Ag  = (const uint4*)(g_aggh + (size_t)row0 * 64);
        uint4*       As4 = (uint4*)As;
        #pragma unroll
        for (int i = 0; i < 8; i++) {
            int idx = i * 256 + tid;          // 0..2047
            int r   = idx >> 4;               // 0..127
            int c   = idx & 15;               // uint4 within row
            As4[r * 17 + c] = Ag[idx];        // 17 uint4 = 136 halfs padded row
        }
    }
    __syncthreads();

    wmma::fragment<wmma::accumulator, 16, 16, 16, float> acc[4][2];
    #pragma unroll
    for (int mf = 0; mf < 4; mf++)
        #pragma unroll
        for (int nf = 0; nf < 2; nf++)
            wmma::fill_fragment(acc[mf][nf], 0.0f);

    const __half* Wh = (const __half*)g_Wh;

    #pragma unroll
    for (int k0 = 0; k0 < 128; k0 += 16) {
        wmma::fragment<wmma::matrix_a, 16, 16, 16, __half, wmma::row_major> af[4];
        #pragma unroll
        for (int mf = 0; mf < 4; mf++)
            wmma::load_matrix_sync(af[mf],
                As + (warp_m * 64 + mf * 16) * 136 + k0, 136);
        #pragma unroll
        for (int nf = 0; nf < 2; nf++) {
            wmma::fragment<wmma::matrix_b, 16, 16, 16, __half, wmma::row_major> bf;
            wmma::load_matrix_sync(bf, Wh + k0 * CH + warp_n * 32 + nf * 16, CH);
            #pragma unroll
            for (int mf = 0; mf < 4; mf++)
                wmma::mma_sync(acc[mf][nf], af[mf], bf, acc[mf][nf]);
        }
    }

    // epilogue: bounce each 16x16 frag through smem, add bias, coalesced store
    float* es = Es + wid * 256;
    #pragma unroll
    for (int mf = 0; mf < 4; mf++) {
        #pragma unroll
        for (int nf = 0; nf < 2; nf++) {
            wmma::store_matrix_sync(es, acc[mf][nf], 16, wmma::mem_row_major);
            __syncwarp();
            int r_in = lane >> 1;
            int c0   = (lane & 1) * 8;
            int gr   = row0 + warp_m * 64 + mf * 16 + r_in;
            int gc   = warp_n * 32 + nf * 16 + c0;
            if (gr < M) {
                float4 b0 = *(const float4*)(bias + gc);
                float4 b1 = *(const float4*)(bias + gc + 4);
                const float* p = es + r_in * 16 + c0;
                float4 o0 = make_float4(p[0] + b0.x, p[1] + b0.y,
                                        p[2] + b0.z, p[3] + b0.w);
                float4 o1 = make_float4(p[4] + b1.x, p[5] + b1.y,
                                        p[6] + b1.z, p[7] + b1.w);
                *(float4*)(C + (size_t)gr * CH + gc)     = o0;
                *(float4*)(C + (size_t)gr * CH + gc + 4) = o1;
            }
            __syncwarp();
        }
    }
}

// ---------------- launch --------------------------------------------------------
extern "C" void kernel_launch(void* const* d_in, const int* in_sizes, int n_in,
                              void* d_out, int out_size) {
    const float* x    = (const float*)d_in[0];
    const int*   ei   = (const int*)d_in[1];     // int32 [2, E]
    const float* W    = (const float*)d_in[2];
    const float* bias = (const float*)d_in[3];
    float*       out  = (float*)d_out;

    int N = in_sizes[0] / CH;   // 100000
    int E = in_sizes[1] / 2;    // 1600000
    int nb = (N + SCAN_BLK - 1) / SCAN_BLK;

    k_prep      <<<(N * 64 + 255) / 256, 256>>>((const float2*)x,
                                                (const float2*)W, N);
    k_count     <<<(E + 255) / 256, 256>>>(ei, E, N);
    k_scan_block<<<nb, SCAN_BLK>>>(N);
    k_scan_bsums<<<1, 256>>>(nb);
    k_scan_add  <<<(N + 255) / 256, 256>>>(N);
    k_fill      <<<(E + 255) / 256, 256>>>(ei, E, N);
    k_aggregate <<<(N * 32 + 255) / 256, 256>>>(N);
    k_gemm      <<<(N + 127) / 128, 256>>>(bias, out, N);
}